// round 15
// baseline (speedup 1.0000x reference)
#include <cuda_runtime.h>
#include <math.h>

#define B 64
#define T 4096
#define D 512
#define NSPLIT 32                // CTAs per batch in partial kernel
#define WARPS 4                  // warps per CTA (128 threads)
#define NPART NSPLIT             // ONE partial per CTA (warps merged in smem)
#define ROWS_PER_WARP 32         // (T/NSPLIT)/WARPS
#define NPAIR (ROWS_PER_WARP/2)  // 16 row pairs per warp

#define KD 32                    // key kernel: d-columns per CTA
#define KB 32                    // key kernel: batches per CTA
#define KZ 16                    // key kernel: split-K factor
#define KSLICE (D / KZ)          // 32 floats per K slice
#define QP4 9                    // smem pitch in float4 (odd -> conflict-free)

// Scratch (static device globals: allocation-free)
__device__ float g_kpart[KZ * B * D];                // 2 MB (split-K partials)
__device__ float g_key[B * D];                       // 128 KB (folded key)
__device__ float g_pm[B * NPART];
__device__ float g_ps[B * NPART];
__device__ float g_pc[(size_t)B * NPART * D];        // 4.2 MB
__device__ int   g_mask_kind;                        // 0=int32, 1=uint8, 2=float32

// ---------------------------------------------------------------------------
// Kernel 1: split-K key GEMM (unchanged).
// ---------------------------------------------------------------------------
__global__ __launch_bounds__(256) void key_kernel(const float* __restrict__ q,
                                                  const float* __restrict__ W,
                                                  const float* __restrict__ bias,
                                                  const unsigned int* __restrict__ mw) {
    if (blockIdx.x == 0 && blockIdx.y == 0 && blockIdx.z == 0) {
        int kind = 0;
        for (int i = threadIdx.x; i < 2048; i += blockDim.x) {
            unsigned int w = mw[i];
            if (w == 0x3f800000u)            kind = 2;                    // float 1.0f
            else if ((w & 0xFFFFFF00u) != 0) kind = kind > 1 ? kind : 1;  // high byte set
        }
        if (kind) atomicMax(&g_mask_kind, kind);   // stays 0 => int32
    }

    __shared__ float4 qs[KB * QP4];

    const int b0 = blockIdx.y * KB;
    const int d0 = blockIdx.x * KD;
    const int k0 = blockIdx.z * KSLICE;

    {
        int row = threadIdx.x >> 3;
        int col = threadIdx.x & 7;
        qs[row * QP4 + col] =
            *reinterpret_cast<const float4*>(q + (size_t)(b0 + row) * D + k0 + 4 * col);
    }
    __syncthreads();

    const int warp = threadIdx.x >> 5;
    const int lane = threadIdx.x & 31;
    const int d    = d0 + warp * 4 + (lane >> 3);
    const int bl   = lane & 7;

    const float4* wrow = reinterpret_cast<const float4*>(W + (size_t)d * D + k0);

    float4 acc[4];
#pragma unroll
    for (int u = 0; u < 4; u++) acc[u] = make_float4(0.f, 0.f, 0.f, 0.f);

#pragma unroll
    for (int j = 0; j < KSLICE / 4; j++) {
        float4 wv = wrow[j];
#pragma unroll
        for (int u = 0; u < 4; u++) {
            float4 qv = qs[(bl + 8 * u) * QP4 + j];
            acc[u].x = fmaf(wv.x, qv.x, acc[u].x);
            acc[u].y = fmaf(wv.y, qv.y, acc[u].y);
            acc[u].z = fmaf(wv.z, qv.z, acc[u].z);
            acc[u].w = fmaf(wv.w, qv.w, acc[u].w);
        }
    }

    const float bd = (blockIdx.z == 0) ? bias[d] : 0.f;
#pragma unroll
    for (int u = 0; u < 4; u++) {
        float r = (acc[u].x + acc[u].y) + (acc[u].z + acc[u].w) + bd;
        g_kpart[blockIdx.z * (B * D) + (size_t)(b0 + bl + 8 * u) * D + d] = r;
    }
}

// ---------------------------------------------------------------------------
// Kernel 1b: fold split-K slices into g_key once (unchanged).
// ---------------------------------------------------------------------------
__global__ __launch_bounds__(256) void fold_kernel() {
    const int i = blockIdx.x * 256 + threadIdx.x;
    float s = 0.f;
#pragma unroll
    for (int z = 0; z < KZ; z++)
        s += g_kpart[z * (B * D) + i];
    g_key[i] = s;
}

// ---------------------------------------------------------------------------
// Kernel 2: per-warp online softmax; DEPTH-2 software pipeline (3 buffer
// slots): pairs i+1 AND i+2 are in flight while pair i is processed, so each
// warp keeps ~8KB outstanding through the serial dot/shuffle/exp chain
// (R14 depth-1 left a ~300cyc exposed wait per pair).
// Batch-2 single-state update (one rescale per pair) as in R14.
// Buffers zero-initialized; stale data in masked slots is finite and
// annihilated by w=0.
// ---------------------------------------------------------------------------
__global__ __launch_bounds__(128) void partial_kernel(const float* __restrict__ A,
                                                      const void* __restrict__ mask_raw) {
    const int b     = blockIdx.x / NSPLIT;
    const int split = blockIdx.x % NSPLIT;
    const int warp  = threadIdx.x >> 5;
    const int lane  = threadIdx.x & 31;
    const int t0    = split * (T / NSPLIT) + warp * ROWS_PER_WARP;

    const size_t midx = (size_t)(t0 + lane) * B + b;
    const int kind = g_mask_kind;
    bool masked;
    if (kind == 1)      masked = ((const unsigned char*)mask_raw)[midx] != 0;
    else if (kind == 0) masked = ((const int*)mask_raw)[midx] != 0;
    else                masked = ((const float*)mask_raw)[midx] != 0.f;
    const unsigned act = ~__ballot_sync(0xffffffffu, masked);   // bit r = row active

    float4 kf[4];
    const float* kb = g_key + b * D + 4 * lane;
#pragma unroll
    for (int j = 0; j < 4; j++)
        kf[j] = *reinterpret_cast<const float4*>(kb + 128 * j);

    float m = -INFINITY, s = 0.f;
    float4 c[4];
#pragma unroll
    for (int j = 0; j < 4; j++) c[j] = make_float4(0.f, 0.f, 0.f, 0.f);

    const float* base = A + ((size_t)b * T + t0) * D + 4 * lane;

    // 3-slot pipeline buffers (zero-init once; stale finite data is harmless)
    float4 bufA[3][4], bufB[3][4];
#pragma unroll
    for (int sl = 0; sl < 3; sl++)
#pragma unroll
        for (int j = 0; j < 4; j++) {
            bufA[sl][j] = make_float4(0.f, 0.f, 0.f, 0.f);
            bufB[sl][j] = make_float4(0.f, 0.f, 0.f, 0.f);
        }

    // prefetch pairs 0 and 1 into slots 0 and 1
#pragma unroll
    for (int p = 0; p < 2; p++) {
        const int r0 = 2 * p;
        if ((act >> r0) & 1u) {
            const float* r = base + (size_t)r0 * D;
#pragma unroll
            for (int j = 0; j < 4; j++)
                bufA[p][j] = __ldcs(reinterpret_cast<const float4*>(r + 128 * j));
        }
        if ((act >> (r0 + 1)) & 1u) {
            const float* r = base + (size_t)(r0 + 1) * D;
#pragma unroll
            for (int j = 0; j < 4; j++)
                bufB[p][j] = __ldcs(reinterpret_cast<const float4*>(r + 128 * j));
        }
    }

#pragma unroll
    for (int i = 0; i < NPAIR; i++) {
        const int rp  = 2 * i;
        const int cur = i % 3;

        // ---- prefetch pair i+2 into slot (i+2)%3 ----
        if (i < NPAIR - 2) {
            const int nxt = (i + 2) % 3;
            const int rq  = rp + 4;
            if ((act >> rq) & 1u) {
                const float* r = base + (size_t)rq * D;
#pragma unroll
                for (int j = 0; j < 4; j++)
                    bufA[nxt][j] = __ldcs(reinterpret_cast<const float4*>(r + 128 * j));
            }
            if ((act >> (rq + 1)) & 1u) {
                const float* r = base + (size_t)(rq + 1) * D;
#pragma unroll
                for (int j = 0; j < 4; j++)
                    bufB[nxt][j] = __ldcs(reinterpret_cast<const float4*>(r + 128 * j));
            }
        }

        // ---- process pair i ----
        const bool doA = (act >> rp) & 1u;        // warp-uniform
        const bool doB = (act >> (rp + 1)) & 1u;  // warp-uniform
        if (doA || doB) {
            float pA = 0.f, pB = 0.f;
            if (doA) {
#pragma unroll
                for (int j = 0; j < 4; j++) {
                    pA = fmaf(bufA[cur][j].x, kf[j].x, pA);
                    pA = fmaf(bufA[cur][j].y, kf[j].y, pA);
                    pA = fmaf(bufA[cur][j].z, kf[j].z, pA);
                    pA = fmaf(bufA[cur][j].w, kf[j].w, pA);
                }
            }
            if (doB) {
#pragma unroll
                for (int j = 0; j < 4; j++) {
                    pB = fmaf(bufB[cur][j].x, kf[j].x, pB);
                    pB = fmaf(bufB[cur][j].y, kf[j].y, pB);
                    pB = fmaf(bufB[cur][j].z, kf[j].z, pB);
                    pB = fmaf(bufB[cur][j].w, kf[j].w, pB);
                }
            }
#pragma unroll
            for (int off = 16; off > 0; off >>= 1) {
                if (doA) pA += __shfl_xor_sync(0xffffffffu, pA, off);
                if (doB) pB += __shfl_xor_sync(0xffffffffu, pB, off);
            }

            // batch-2 single-state online softmax update
            float mn = m;
            if (doA) mn = fmaxf(mn, pA);
            if (doB) mn = fmaxf(mn, pB);
            const float alpha = __expf(m - mn);              // m=-inf -> 0
            const float wA = doA ? __expf(pA - mn) : 0.f;
            const float wB = doB ? __expf(pB - mn) : 0.f;
            s = s * alpha + wA + wB;
#pragma unroll
            for (int j = 0; j < 4; j++) {
                c[j].x = fmaf(wB, bufB[cur][j].x, fmaf(wA, bufA[cur][j].x, c[j].x * alpha));
                c[j].y = fmaf(wB, bufB[cur][j].y, fmaf(wA, bufA[cur][j].y, c[j].y * alpha));
                c[j].z = fmaf(wB, bufB[cur][j].z, fmaf(wA, bufA[cur][j].z, c[j].z * alpha));
                c[j].w = fmaf(wB, bufB[cur][j].w, fmaf(wA, bufA[cur][j].w, c[j].w * alpha));
            }
            m = mn;
        }
    }

    // ---- CTA-level merge of the 4 warp states (smem) ----
    __shared__ float sm_m[WARPS], sm_s[WARPS];
    __shared__ float sm_c[WARPS][D];
    if (lane == 0) { sm_m[warp] = m; sm_s[warp] = s; }
    __syncthreads();
    const float M = fmaxf(fmaxf(sm_m[0], sm_m[1]), fmaxf(sm_m[2], sm_m[3]));
    const float myscale = (m == -INFINITY) ? 0.f : __expf(m - M);
    float* cw = &sm_c[warp][4 * lane];
#pragma unroll
    for (int j = 0; j < 4; j++) {
        float4 v = c[j];
        v.x *= myscale; v.y *= myscale; v.z *= myscale; v.w *= myscale;
        *reinterpret_cast<float4*>(cw + 128 * j) = v;
    }
    __syncthreads();

    const int pid = blockIdx.x;   // b*NSPLIT + split
    if (threadIdx.x == 0) {
        float st = 0.f;
#pragma unroll
        for (int w = 0; w < WARPS; w++) {
            float sc = (sm_m[w] == -INFINITY) ? 0.f : __expf(sm_m[w] - M);
            st += sm_s[w] * sc;
        }
        g_pm[pid] = M;
        g_ps[pid] = st;
    }
    float* pc = g_pc + (size_t)pid * D;
#pragma unroll
    for (int j = 0; j < 4; j++) {
        int col = threadIdx.x + 128 * j;
        pc[col] = ((sm_c[0][col] + sm_c[1][col]) + (sm_c[2][col] + sm_c[3][col]));
    }
}

// ---------------------------------------------------------------------------
// Kernel 3: combine 32 partials per batch.  REWORKED again: grid B*8 CTAs x
// 128 threads = 2 threads per column (each sums 16 partials), combined in
// smem. Halves the serial load chain that kept R14's version at 643GB/s.
// ---------------------------------------------------------------------------
__global__ __launch_bounds__(128) void reduce_kernel(float* __restrict__ out) {
    const int b    = blockIdx.x >> 3;
    const int part = blockIdx.x & 7;
    const int tid  = threadIdx.x;
    const int col  = tid & 63;     // column within this CTA's 64
    const int half = tid >> 6;     // 0 or 1: which 16 partials

    __shared__ float sc[NPART];
    __shared__ float Ssh;
    __shared__ float ps[128];

    if (tid < 32) {
        const float mi = g_pm[b * NPART + tid];
        float mm = mi;
#pragma unroll
        for (int off = 16; off > 0; off >>= 1)
            mm = fmaxf(mm, __shfl_xor_sync(0xffffffffu, mm, off));
        const float scale = (mi == -INFINITY) ? 0.f : __expf(mi - mm);
        sc[tid] = scale;
        float sv = scale * g_ps[b * NPART + tid];
#pragma unroll
        for (int off = 16; off > 0; off >>= 1)
            sv += __shfl_xor_sync(0xffffffffu, sv, off);
        if (tid == 0) Ssh = sv;
    }
    __syncthreads();

    const int d  = part * 64 + col;
    const int i0 = half * 16;
    float acc = 0.f;
    const float* pc = g_pc + (size_t)b * NPART * D + d;
#pragma unroll
    for (int i = 0; i < 16; i++)
        acc = fmaf(pc[(size_t)(i0 + i) * D], sc[i0 + i], acc);
    ps[tid] = acc;
    __syncthreads();
    if (half == 0)
        out[b * D + d] = (ps[tid] + ps[tid + 64]) / Ssh;
}

// ---------------------------------------------------------------------------
extern "C" void kernel_launch(void* const* d_in, const int* in_sizes, int n_in,
                              void* d_out, int out_size) {
    const float* q    = (const float*)d_in[0];   // [B, D]
    const float* A    = (const float*)d_in[1];   // [B, T, D]
    const void*  mask = d_in[2];                 // [T, B] bool-ish (dtype sniffed)
    const float* W    = (const float*)d_in[3];   // [D, D]
    const float* bias = (const float*)d_in[4];   // [D]
    float*       out  = (float*)d_out;           // [B, 1, D]

    key_kernel<<<dim3(D / KD, B / KB, KZ), 256>>>(q, W, bias, (const unsigned int*)mask);
    fold_kernel<<<(B * D) / 256, 256>>>();
    partial_kernel<<<B * NSPLIT, WARPS * 32>>>(A, mask);
    reduce_kernel<<<B * 8, 128>>>(out);
}